// round 8
// baseline (speedup 1.0000x reference)
#include <cuda_runtime.h>
#include <cuda_fp16.h>
#include <cstdint>

#define B2   8192
#define D    512
#define NM1  8191

#define TM   256
#define TN   128
#define NSTG 3
#define NCH  32        // 16 int8 chunks (cross, K=2048B) + 16 fp16 chunks (hihi)

#define ROWB 144                       // 128 B data + 16 B pad (ldmatrix conflict-free)
#define A_SZ (256 * ROWB)              // 36864
#define B_SZ (128 * ROWB)              // 18432
#define STAGE_SZ (A_SZ + B_SZ)         // 55296
#define SM_TOTAL (NSTG * STAGE_SZ)     // 165888

#define CSCALE (1.0f / 65536.0f)       // (2^-2)*(2^-14) shared segment scale

// ---------------- device scratch ----------------
__device__ __align__(128) __half g_Ah[(size_t)B2 * 1024];  // [hi(x^2) | hi(x)]
__device__ __align__(128) __half g_Bh[(size_t)B2 * 1024];  // [hi(1/s) | hi(-2x/s)]
__device__ __align__(128) char   g_A8[(size_t)B2 * 2048];  // [qH(a) | qL(a)]
__device__ __align__(128) char   g_B8[(size_t)B2 * 2048];  // [qL(b) | qH(b)]
__device__ float g_t3[B2];
__device__ float g_ls[B2];
__device__ float g_c[B2];      // 0.1*gt_i + 0.5*ls_i
__device__ float g_cj[B2];     // -0.5*ls[pos(j)] - 0.1*t3[j]
__device__ float g_rowsum[B2];

// ---------------- PTX helpers ----------------
__device__ __forceinline__ uint32_t smem_u32(const void* p) {
    uint32_t a;
    asm("{ .reg .u64 t; cvta.to.shared.u64 t, %1; cvt.u32.u64 %0, t; }" : "=r"(a) : "l"(p));
    return a;
}
__device__ __forceinline__ void cp_async16(uint32_t dst, const void* src) {
    asm volatile("cp.async.cg.shared.global [%0], [%1], 16;" :: "r"(dst), "l"(src) : "memory");
}
__device__ __forceinline__ void cp_commit() {
    asm volatile("cp.async.commit_group;" ::: "memory");
}
template <int N> __device__ __forceinline__ void cp_wait() {
    asm volatile("cp.async.wait_group %0;" :: "n"(N) : "memory");
}
__device__ __forceinline__ void ldsm4(uint32_t addr, uint32_t* r) {
    asm volatile("ldmatrix.sync.aligned.m8n8.x4.shared.b16 {%0,%1,%2,%3}, [%4];"
                 : "=r"(r[0]), "=r"(r[1]), "=r"(r[2]), "=r"(r[3]) : "r"(addr));
}
// fp16 MMA: m16n8k16 f32 accum
__device__ __forceinline__ void hmma16816(float* d, const uint32_t* a,
                                          uint32_t b0, uint32_t b1) {
    asm volatile(
        "mma.sync.aligned.m16n8k16.row.col.f32.f16.f16.f32 "
        "{%0,%1,%2,%3}, {%4,%5,%6,%7}, {%8,%9}, {%0,%1,%2,%3};"
        : "+f"(d[0]), "+f"(d[1]), "+f"(d[2]), "+f"(d[3])
        : "r"(a[0]), "r"(a[1]), "r"(a[2]), "r"(a[3]), "r"(b0), "r"(b1));
}
// int8 MMA: m16n8k32 s32 accum
__device__ __forceinline__ void imma16832(int* d, const uint32_t* a,
                                          uint32_t b0, uint32_t b1) {
    asm volatile(
        "mma.sync.aligned.m16n8k32.row.col.s32.s8.s8.s32 "
        "{%0,%1,%2,%3}, {%4,%5,%6,%7}, {%8,%9}, {%0,%1,%2,%3};"
        : "+r"(d[0]), "+r"(d[1]), "+r"(d[2]), "+r"(d[3])
        : "r"(a[0]), "r"(a[1]), "r"(a[2]), "r"(a[3]), "r"(b0), "r"(b1));
}

// ---------------- prep: fp16/int8 splits + t3 + ls ----------------
__device__ __forceinline__ void split_store(float v, __half* ph, char* pqh, char* pql) {
    __half h = __float2half_rn(v);
    float hf = __half2float(h);
    float lo = v - hf;
    *ph = h;
    int qh = __float2int_rn(hf * 4.0f);
    int ql = __float2int_rn(lo * 16384.0f);
    qh = max(-127, min(127, qh));
    ql = max(-127, min(127, ql));
    *pqh = (char)qh;
    *pql = (char)ql;
}

__global__ void prep_kernel(const float* __restrict__ f, const float* __restrict__ s) {
    int i = blockIdx.x;
    int t = threadIdx.x;  // 128
    const float* fr = f + (size_t)i * D;
    const float* sr = s + (size_t)i * D;
    __half* Ah = g_Ah + (size_t)i * 1024;
    __half* Bh = g_Bh + (size_t)i * 1024;
    char*   A8 = g_A8 + (size_t)i * 2048;
    char*   B8 = g_B8 + (size_t)i * 2048;
    float t3p = 0.f, lsp = 0.f;
    for (int d = t; d < D; d += 128) {
        float x = fr[d], sg = sr[d];
        float inv = 1.0f / sg;
        float a1 = x * x, a2 = x, b1 = inv, b2 = -2.0f * x * inv;
        // A: [qH | qL],  B: [qL | qH]
        split_store(a1, Ah + d,       A8 + d,        A8 + 1024 + d);
        split_store(a2, Ah + 512 + d, A8 + 512 + d,  A8 + 1536 + d);
        split_store(b1, Bh + d,       B8 + 1024 + d, B8 + d);
        split_store(b2, Bh + 512 + d, B8 + 1536 + d, B8 + 512 + d);
        t3p += a1 * inv;
        lsp += __logf(sg);
    }
    __shared__ float sh1[128], sh2[128];
    sh1[t] = t3p; sh2[t] = lsp;
    __syncthreads();
    for (int st = 64; st > 0; st >>= 1) {
        if (t < st) { sh1[t] += sh1[t + st]; sh2[t] += sh2[t + st]; }
        __syncthreads();
    }
    if (t == 0) { g_t3[i] = sh1[0]; g_ls[i] = sh2[0]; g_rowsum[i] = 0.f; }
}

// ---------------- gt + per-row/col constants (fp32 exact) ----------------
__global__ void gt_kernel(const float* __restrict__ f, const float* __restrict__ s,
                          const int* __restrict__ label) {
    int i = blockIdx.x;
    int lab = label[i];
    int pos = lab + (lab >= i ? 1 : 0);
    const float* xi = f + (size_t)i * D;
    const float* xp = f + (size_t)pos * D;
    const float* sp = s + (size_t)pos * D;
    float p = 0.f;
    for (int d = threadIdx.x; d < D; d += 256) {
        float dd = xi[d] - xp[d];
        p += dd * dd / sp[d];
    }
    __shared__ float sh[256];
    sh[threadIdx.x] = p;
    __syncthreads();
    for (int st = 128; st > 0; st >>= 1) {
        if (threadIdx.x < st) sh[threadIdx.x] += sh[threadIdx.x + st];
        __syncthreads();
    }
    if (threadIdx.x == 0) {
        g_c[i]  = 0.1f * sh[0] + 0.5f * g_ls[i];
        g_cj[i] = -0.5f * g_ls[pos] - 0.1f * g_t3[i];
    }
}

// ---------------- chunk loader: 128 B per row per chunk ----------------
// chunks 0..15: int8 cross operands; 16..31: fp16 hi operands (same byte geometry)
__device__ __forceinline__ void load_chunk(int c, int st, int i0, int j0, uint32_t sb) {
    const char* baseA = (c < 16) ? g_A8 : (const char*)g_Ah;
    const char* baseB = (c < 16) ? g_B8 : (const char*)g_Bh;
    const int col = (c & 15) * 128;           // byte column within 2048 B row
    const uint32_t aS = sb + st * STAGE_SZ;
    const uint32_t bS = aS + A_SZ;
    const int tid = threadIdx.x;
#pragma unroll
    for (int it = 0; it < 8; it++) {          // A: 2048 x 16B
        int id = tid + it * 256;
        int row = id >> 3, kc = id & 7;
        cp_async16(aS + row * ROWB + kc * 16,
                   baseA + (size_t)(i0 + row) * 2048 + col + kc * 16);
    }
#pragma unroll
    for (int it = 0; it < 4; it++) {          // B: 1024 x 16B
        int id = tid + it * 256;
        int row = id >> 3, kc = id & 7;
        cp_async16(bS + row * ROWB + kc * 16,
                   baseB + (size_t)(j0 + row) * 2048 + col + kc * 16);
    }
}

// ---------------- main mixed-precision dist kernel ----------------
__global__ __launch_bounds__(256)
void dist_kernel(float* __restrict__ out, int write_logits) {
    extern __shared__ char smem[];
    const uint32_t sb = smem_u32(smem);
    const int tid  = threadIdx.x;
    const int lane = tid & 31;
    const int wid  = tid >> 5;
    const int wm   = wid & 3;        // 4 M groups of 64
    const int wn   = wid >> 2;       // 2 N groups of 64
    const int i0 = blockIdx.y * TM;
    const int j0 = blockIdx.x * TN;

    const uint32_t aoff = (wm * 64 + (lane & 15)) * ROWB + (lane >> 4) * 16;
    const uint32_t boff = (wn * 64 + (lane & 15)) * ROWB + (lane >> 4) * 16;

    // prologue: stages 0,1
#pragma unroll
    for (int s = 0; s < NSTG - 1; s++) { load_chunk(s, s, i0, j0, sb); cp_commit(); }

    uint32_t afr[2][4][4], bfr[2][4][4];

    // ---------------- phase 1: int8 cross GEMM (chunks 0..15) ----------------
    int acci[4][8][4];
#pragma unroll
    for (int mi = 0; mi < 4; mi++)
#pragma unroll
        for (int ni = 0; ni < 8; ni++)
#pragma unroll
            for (int q = 0; q < 4; q++) acci[mi][ni][q] = 0;

    for (int c = 0; c < 16; c++) {
        cp_wait<1>();
        __syncthreads();
        int pf = c + NSTG - 1;
        load_chunk(pf, pf % NSTG, i0, j0, sb);
        cp_commit();

        const uint32_t aS = sb + (c % NSTG) * STAGE_SZ;
        const uint32_t bS = aS + A_SZ;
#pragma unroll
        for (int mi = 0; mi < 4; mi++) ldsm4(aS + aoff + mi * (16 * ROWB), afr[0][mi]);
#pragma unroll
        for (int np = 0; np < 4; np++) ldsm4(bS + boff + np * (16 * ROWB), bfr[0][np]);
#pragma unroll
        for (int ks = 0; ks < 4; ks++) {       // 4 x k32 (32 B each)
            const int cur = ks & 1, nxt = cur ^ 1;
            if (ks < 3) {
#pragma unroll
                for (int mi = 0; mi < 4; mi++)
                    ldsm4(aS + aoff + mi * (16 * ROWB) + (ks + 1) * 32, afr[nxt][mi]);
#pragma unroll
                for (int np = 0; np < 4; np++)
                    ldsm4(bS + boff + np * (16 * ROWB) + (ks + 1) * 32, bfr[nxt][np]);
            }
#pragma unroll
            for (int mi = 0; mi < 4; mi++)
#pragma unroll
                for (int ni = 0; ni < 8; ni++)
                    imma16832(acci[mi][ni], afr[cur][mi],
                              bfr[cur][ni >> 1][ni & 1], bfr[cur][ni >> 1][(ni & 1) + 2]);
        }
    }

    // convert cross-term to float (shared pow2 scale)
    float acc[4][8][4];
#pragma unroll
    for (int mi = 0; mi < 4; mi++)
#pragma unroll
        for (int ni = 0; ni < 8; ni++)
#pragma unroll
            for (int q = 0; q < 4; q++) acc[mi][ni][q] = (float)acci[mi][ni][q] * CSCALE;

    // ---------------- phase 2: fp16 hi*hi GEMM (chunks 16..31) ----------------
    for (int c = 16; c < 32; c++) {
        cp_wait<1>();
        __syncthreads();
        int pf = c + NSTG - 1;
        if (pf < NCH) { load_chunk(pf, pf % NSTG, i0, j0, sb); cp_commit(); }
        else cp_commit();

        const uint32_t aS = sb + (c % NSTG) * STAGE_SZ;
        const uint32_t bS = aS + A_SZ;
#pragma unroll
        for (int mi = 0; mi < 4; mi++) ldsm4(aS + aoff + mi * (16 * ROWB), afr[0][mi]);
#pragma unroll
        for (int np = 0; np < 4; np++) ldsm4(bS + boff + np * (16 * ROWB), bfr[0][np]);
#pragma unroll
        for (int ks = 0; ks < 4; ks++) {       // 4 x k16 (32 B each)
            const int cur = ks & 1, nxt = cur ^ 1;
            if (ks < 3) {
#pragma unroll
                for (int mi = 0; mi < 4; mi++)
                    ldsm4(aS + aoff + mi * (16 * ROWB) + (ks + 1) * 32, afr[nxt][mi]);
#pragma unroll
                for (int np = 0; np < 4; np++)
                    ldsm4(bS + boff + np * (16 * ROWB) + (ks + 1) * 32, bfr[nxt][np]);
            }
#pragma unroll
            for (int mi = 0; mi < 4; mi++)
#pragma unroll
                for (int ni = 0; ni < 8; ni++)
                    hmma16816(acc[mi][ni], afr[cur][mi],
                              bfr[cur][ni >> 1][ni & 1], bfr[cur][ni >> 1][(ni & 1) + 2]);
        }
    }

    // ---------------- epilogue ----------------
    float cv0[4], cv1[4];
#pragma unroll
    for (int mi = 0; mi < 4; mi++) {
        int r0 = i0 + wm * 64 + mi * 16 + (lane >> 2);
        cv0[mi] = g_c[r0];
        cv1[mi] = g_c[r0 + 8];
    }
    float cjv[8][2];
#pragma unroll
    for (int ni = 0; ni < 8; ni++) {
        int cb = j0 + wn * 64 + (ni >> 1) * 16 + (ni & 1) * 8 + (lane & 3) * 2;
        cjv[ni][0] = g_cj[cb];
        cjv[ni][1] = g_cj[cb + 1];
    }

#pragma unroll
    for (int mi = 0; mi < 4; mi++) {
        const int r0 = i0 + wm * 64 + mi * 16 + (lane >> 2);
        const int r1 = r0 + 8;
        float rs0 = 0.f, rs1 = 0.f;
#pragma unroll
        for (int ni = 0; ni < 8; ni++) {
            const int cb = j0 + wn * 64 + (ni >> 1) * 16 + (ni & 1) * 8 + (lane & 3) * 2;
            float e0 = __expf(cv0[mi] + cjv[ni][0] - 0.1f * acc[mi][ni][0]);
            float e1 = __expf(cv0[mi] + cjv[ni][1] - 0.1f * acc[mi][ni][1]);
            float e2 = __expf(cv1[mi] + cjv[ni][0] - 0.1f * acc[mi][ni][2]);
            float e3 = __expf(cv1[mi] + cjv[ni][1] - 0.1f * acc[mi][ni][3]);
            if (cb     == r0) e0 = 0.f;
            if (cb + 1 == r0) e1 = 0.f;
            if (cb     == r1) e2 = 0.f;
            if (cb + 1 == r1) e3 = 0.f;
            rs0 += e0 + e1;
            rs1 += e2 + e3;
            if (write_logits) {
                if (cb     != r0) out[(size_t)r0 * NM1 + cb     - (cb     > r0)] = e0;
                if (cb + 1 != r0) out[(size_t)r0 * NM1 + cb + 1 - (cb + 1 > r0)] = e1;
                if (cb     != r1) out[(size_t)r1 * NM1 + cb     - (cb     > r1)] = e2;
                if (cb + 1 != r1) out[(size_t)r1 * NM1 + cb + 1 - (cb + 1 > r1)] = e3;
            }
        }
        rs0 += __shfl_xor_sync(0xFFFFFFFFu, rs0, 1);
        rs0 += __shfl_xor_sync(0xFFFFFFFFu, rs0, 2);
        rs1 += __shfl_xor_sync(0xFFFFFFFFu, rs1, 1);
        rs1 += __shfl_xor_sync(0xFFFFFFFFu, rs1, 2);
        if ((lane & 3) == 0) {
            atomicAdd(&g_rowsum[r0], rs0);
            atomicAdd(&g_rowsum[r1], rs1);
        }
    }
}

// ---------------- loss = mean(log(rowsum)) ----------------
__global__ void loss_kernel(float* __restrict__ loss_out) {
    __shared__ float sh[1024];
    float p = 0.f;
    for (int i = threadIdx.x; i < B2; i += 1024) p += __logf(g_rowsum[i]);
    sh[threadIdx.x] = p;
    __syncthreads();
    for (int st = 512; st > 0; st >>= 1) {
        if (threadIdx.x < st) sh[threadIdx.x] += sh[threadIdx.x + st];
        __syncthreads();
    }
    if (threadIdx.x == 0) *loss_out = sh[0] / (float)B2;
}

// ---------------- launch ----------------
extern "C" void kernel_launch(void* const* d_in, const int* in_sizes, int n_in,
                              void* d_out, int out_size) {
    const float* f     = (const float*)d_in[0];
    const float* s     = (const float*)d_in[1];
    const int*   label = (const int*)d_in[2];

    float* outf = (float*)d_out;
    const long long LOGN = (long long)B2 * NM1;
    float* loss_out  = nullptr;
    float* logit_out = nullptr;
    if ((long long)out_size == LOGN + 1) { loss_out = outf; logit_out = outf + 1; }
    else if ((long long)out_size == LOGN) { logit_out = outf; }
    else { loss_out = outf; }

    cudaFuncSetAttribute(dist_kernel, cudaFuncAttributeMaxDynamicSharedMemorySize, SM_TOTAL);

    prep_kernel<<<B2, 128>>>(f, s);
    gt_kernel<<<B2, 256>>>(f, s, label);

    dim3 grid(B2 / TN, B2 / TM);
    dist_kernel<<<grid, 256, SM_TOTAL>>>(logit_out ? logit_out : outf,
                                         logit_out != nullptr ? 1 : 0);

    if (loss_out) loss_kernel<<<1, 1024>>>(loss_out);
}

// round 9
// speedup vs baseline: 1.0511x; 1.0511x over previous
#include <cuda_runtime.h>
#include <cuda_bf16.h>
#include <cstdint>

#define B2   8192
#define D    512
#define KD   2048      // bf16 cols: [0,1024) hi, [1024,2048) lo
#define NM1  8191

#define TM   256
#define TN   128
#define BK   64        // bf16 per chunk (128 B rows)
#define NSTG 3
#define NCH  36        // 3 products * 6 chunks (feat 0..383, both halves)
#define NFD  128       // exact fp32 feature dims [384,512)

#define ROWB 144                       // 128 B data + 16 B pad
#define A_SZ (256 * ROWB)              // 36864
#define B_SZ (128 * ROWB)              // 18432
#define FP_OFF (A_SZ + B_SZ)           // 55296 (16B aligned)
#define FP_SZ  (4 * 384 * 8)           // up to 4 d-slices * (256+128) float2 = 12288
#define STAGE_SZ (FP_OFF + FP_SZ)      // 67584
#define SM_TOTAL (NSTG * STAGE_SZ)     // 202752

// ---------------- device scratch ----------------
__device__ __align__(128) __nv_bfloat16 g_Abf[(size_t)B2 * KD];
__device__ __align__(128) __nv_bfloat16 g_Bbf[(size_t)B2 * KD];
__device__ __align__(128) float2 g_A32[(size_t)NFD * B2];  // (x^2, x) for d in [384,512)
__device__ __align__(128) float2 g_B32[(size_t)NFD * B2];  // (1/s, -2x/s)
__device__ float g_t3[B2];
__device__ float g_ls[B2];
__device__ float g_c[B2];      // 0.1*gt_i + 0.5*ls_i
__device__ float g_cj[B2];     // -0.5*ls[pos(j)] - 0.1*t3[j]
__device__ float g_rowsum[B2];

// ---------------- PTX helpers ----------------
__device__ __forceinline__ uint32_t smem_u32(const void* p) {
    uint32_t a;
    asm("{ .reg .u64 t; cvta.to.shared.u64 t, %1; cvt.u32.u64 %0, t; }" : "=r"(a) : "l"(p));
    return a;
}
__device__ __forceinline__ void cp_async16(uint32_t dst, const void* src) {
    asm volatile("cp.async.cg.shared.global [%0], [%1], 16;" :: "r"(dst), "l"(src) : "memory");
}
__device__ __forceinline__ void cp_async8(uint32_t dst, const void* src) {
    asm volatile("cp.async.ca.shared.global [%0], [%1], 8;" :: "r"(dst), "l"(src) : "memory");
}
__device__ __forceinline__ void cp_commit() {
    asm volatile("cp.async.commit_group;" ::: "memory");
}
template <int N> __device__ __forceinline__ void cp_wait() {
    asm volatile("cp.async.wait_group %0;" :: "n"(N) : "memory");
}
__device__ __forceinline__ void ldsm4(uint32_t addr, uint32_t* r) {
    asm volatile("ldmatrix.sync.aligned.m8n8.x4.shared.b16 {%0,%1,%2,%3}, [%4];"
                 : "=r"(r[0]), "=r"(r[1]), "=r"(r[2]), "=r"(r[3]) : "r"(addr));
}
__device__ __forceinline__ void mma16816(float* d, const uint32_t* a,
                                         uint32_t b0, uint32_t b1) {
    asm volatile(
        "mma.sync.aligned.m16n8k16.row.col.f32.bf16.bf16.f32 "
        "{%0,%1,%2,%3}, {%4,%5,%6,%7}, {%8,%9}, {%0,%1,%2,%3};"
        : "+f"(d[0]), "+f"(d[1]), "+f"(d[2]), "+f"(d[3])
        : "r"(a[0]), "r"(a[1]), "r"(a[2]), "r"(a[3]), "r"(b0), "r"(b1));
}

// ---------------- prep: bf16 splits + fp32 tail dims + t3 + ls ----------------
__global__ void prep_kernel(const float* __restrict__ f, const float* __restrict__ s) {
    int i = blockIdx.x;
    int t = threadIdx.x;  // 128
    const float* fr = f + (size_t)i * D;
    const float* sr = s + (size_t)i * D;
    __nv_bfloat16* Ar = g_Abf + (size_t)i * KD;
    __nv_bfloat16* Br = g_Bbf + (size_t)i * KD;
    float t3p = 0.f, lsp = 0.f;
    for (int d = t; d < D; d += 128) {
        float x = fr[d], sg = sr[d];
        float inv = 1.0f / sg;
        float a1 = x * x, a2 = x, b1 = inv, b2 = -2.0f * x * inv;
        __nv_bfloat16 h;
        h = __float2bfloat16(a1); Ar[d]       = h; Ar[1024 + d] = __float2bfloat16(a1 - __bfloat162float(h));
        h = __float2bfloat16(a2); Ar[512 + d] = h; Ar[1536 + d] = __float2bfloat16(a2 - __bfloat162float(h));
        h = __float2bfloat16(b1); Br[d]       = h; Br[1024 + d] = __float2bfloat16(b1 - __bfloat162float(h));
        h = __float2bfloat16(b2); Br[512 + d] = h; Br[1536 + d] = __float2bfloat16(b2 - __bfloat162float(h));
        if (d >= 384) {
            g_A32[(size_t)(d - 384) * B2 + i] = make_float2(a1, a2);
            g_B32[(size_t)(d - 384) * B2 + i] = make_float2(b1, b2);
        }
        t3p += a1 * inv;
        lsp += __logf(sg);
    }
    __shared__ float sh1[128], sh2[128];
    sh1[t] = t3p; sh2[t] = lsp;
    __syncthreads();
    for (int st = 64; st > 0; st >>= 1) {
        if (t < st) { sh1[t] += sh1[t + st]; sh2[t] += sh2[t + st]; }
        __syncthreads();
    }
    if (t == 0) { g_t3[i] = sh1[0]; g_ls[i] = sh2[0]; g_rowsum[i] = 0.f; }
}

// ---------------- gt + per-row/col constants ----------------
__global__ void gt_kernel(const float* __restrict__ f, const float* __restrict__ s,
                          const int* __restrict__ label) {
    int i = blockIdx.x;
    int lab = label[i];
    int pos = lab + (lab >= i ? 1 : 0);
    const float* xi = f + (size_t)i * D;
    const float* xp = f + (size_t)pos * D;
    const float* sp = s + (size_t)pos * D;
    float p = 0.f;
    for (int d = threadIdx.x; d < D; d += 256) {
        float dd = xi[d] - xp[d];
        p += dd * dd / sp[d];
    }
    __shared__ float sh[256];
    sh[threadIdx.x] = p;
    __syncthreads();
    for (int st = 128; st > 0; st >>= 1) {
        if (threadIdx.x < st) sh[threadIdx.x] += sh[threadIdx.x + st];
        __syncthreads();
    }
    if (threadIdx.x == 0) {
        g_c[i]  = 0.1f * sh[0] + 0.5f * g_ls[i];
        g_cj[i] = -0.5f * g_ls[pos] - 0.1f * g_t3[i];
    }
}

// d-slice schedule: exactly NFD slices over NCH chunks, cnt in {3,4}
__device__ __forceinline__ int d_start(int c) { return (c * NFD) / NCH; }
__device__ __forceinline__ int d_count(int c) { return ((c + 1) * NFD) / NCH - (c * NFD) / NCH; }

// ---------------- chunk loader (bf16 tiles + fp32 slices) ----------------
__device__ __forceinline__ void load_chunk(int c, int st, int i0, int j0, uint32_t sb) {
    const int p   = c / 12;
    const int c12 = c % 12;
    const int base = (c12 < 6) ? c12 * BK : 512 + (c12 - 6) * BK;
    const int acol = (p == 2 ? 1024 : 0) + base;
    const int bcol = (p == 1 ? 1024 : 0) + base;
    const uint32_t aS = sb + st * STAGE_SZ;
    const uint32_t bS = aS + A_SZ;
    const int tid = threadIdx.x;
#pragma unroll
    for (int it = 0; it < 8; it++) {            // A: 2048 16B segs
        int id = tid + it * 256;
        int row = id >> 3, kc = id & 7;
        cp_async16(aS + row * ROWB + kc * 16,
                   g_Abf + (size_t)(i0 + row) * KD + acol + kc * 8);
    }
#pragma unroll
    for (int it = 0; it < 4; it++) {            // B: 1024 16B segs
        int id = tid + it * 256;
        int row = id >> 3, kc = id & 7;
        cp_async16(bS + row * ROWB + kc * 16,
                   g_Bbf + (size_t)(j0 + row) * KD + bcol + kc * 8);
    }
    // fp32 exact-dim slices for this chunk
    const int d0  = d_start(c);
    const int cnt = d_count(c);
    const uint32_t fS = aS + FP_OFF;
    for (int idx = tid; idx < cnt * 384; idx += 256) {
        int dd = idx / 384;
        int e  = idx - dd * 384;
        const float2* src = (e < 256)
            ? &g_A32[(size_t)(d0 + dd) * B2 + i0 + e]
            : &g_B32[(size_t)(d0 + dd) * B2 + j0 + (e - 256)];
        cp_async8(fS + (dd * 384 + e) * 8, src);
    }
}

// ---------------- main hybrid HMMA + FFMA dist kernel ----------------
__global__ __launch_bounds__(256)
void dist_kernel(float* __restrict__ out, int write_logits) {
    extern __shared__ char smem[];
    const uint32_t sb = smem_u32(smem);
    const int tid  = threadIdx.x;
    const int lane = tid & 31;
    const int wid  = tid >> 5;
    const int wm   = wid & 3;        // 4 M groups of 64
    const int wn   = wid >> 2;       // 2 N groups of 64
    const int i0 = blockIdx.y * TM;
    const int j0 = blockIdx.x * TN;

    float acc[4][8][4];
#pragma unroll
    for (int mi = 0; mi < 4; mi++)
#pragma unroll
        for (int ni = 0; ni < 8; ni++)
#pragma unroll
            for (int q = 0; q < 4; q++) acc[mi][ni][q] = 0.f;

    // prologue: stages 0,1
#pragma unroll
    for (int s = 0; s < NSTG - 1; s++) { load_chunk(s, s, i0, j0, sb); cp_commit(); }

    const uint32_t aoff = (wm * 64 + (lane & 15)) * ROWB + (lane >> 4) * 16;
    const uint32_t boff = (wn * 64 + (lane & 15)) * ROWB + (lane >> 4) * 16;
    const int fmaOrderFirst = wid & 1;   // stagger pipes between warps

    uint32_t afr[2][4][4], bfr[2][4][4];

    for (int c = 0; c < NCH; c++) {
        cp_wait<1>();
        __syncthreads();
        int pf = c + NSTG - 1;
        if (pf < NCH) { load_chunk(pf, pf % NSTG, i0, j0, sb); cp_commit(); }

        const uint32_t aS = sb + (c % NSTG) * STAGE_SZ;
        const uint32_t bS = aS + A_SZ;
        const char*    fB = smem + (c % NSTG) * STAGE_SZ + FP_OFF;
        const int cnt = d_count(c);

        // load ks=0 fragments
#pragma unroll
        for (int mi = 0; mi < 4; mi++) ldsm4(aS + aoff + mi * (16 * ROWB), afr[0][mi]);
#pragma unroll
        for (int np = 0; np < 4; np++) ldsm4(bS + boff + np * (16 * ROWB), bfr[0][np]);

#pragma unroll
        for (int ks = 0; ks < 4; ks++) {
            const int cur = ks & 1, nxt = cur ^ 1;
            if (ks < 3) {
#pragma unroll
                for (int mi = 0; mi < 4; mi++)
                    ldsm4(aS + aoff + mi * (16 * ROWB) + (ks + 1) * 32, afr[nxt][mi]);
#pragma unroll
                for (int np = 0; np < 4; np++)
                    ldsm4(bS + boff + np * (16 * ROWB) + (ks + 1) * 32, bfr[nxt][np]);
            }
            // interleave one fp32 d-slice with this ks's MMAs; alternate order by warp
#pragma unroll
            for (int half = 0; half < 2; half++) {
                if ((half ^ fmaOrderFirst) == 0) {
                    // ---- MMA section ----
#pragma unroll
                    for (int mi = 0; mi < 4; mi++)
#pragma unroll
                        for (int ni = 0; ni < 8; ni++)
                            mma16816(acc[mi][ni], afr[cur][mi],
                                     bfr[cur][ni >> 1][ni & 1], bfr[cur][ni >> 1][(ni & 1) + 2]);
                } else if (ks < cnt) {
                    // ---- FFMA section: exact fp32 slice ks ----
                    const float2* Af = (const float2*)(fB + ks * 3072);
                    const float4* Bf = (const float4*)(fB + ks * 3072 + 2048);
                    float2 av[4][2];
#pragma unroll
                    for (int mi = 0; mi < 4; mi++) {
                        int r = wm * 64 + mi * 16 + (lane >> 2);
                        av[mi][0] = Af[r];
                        av[mi][1] = Af[r + 8];
                    }
#pragma unroll
                    for (int ni = 0; ni < 8; ni++) {
                        int cb = wn * 64 + (ni >> 1) * 16 + (ni & 1) * 8 + (lane & 3) * 2;
                        float4 bv = Bf[cb >> 1];
#pragma unroll
                        for (int mi = 0; mi < 4; mi++) {
                            acc[mi][ni][0] = fmaf(av[mi][0].x, bv.x, fmaf(av[mi][0].y, bv.y, acc[mi][ni][0]));
                            acc[mi][ni][1] = fmaf(av[mi][0].x, bv.z, fmaf(av[mi][0].y, bv.w, acc[mi][ni][1]));
                            acc[mi][ni][2] = fmaf(av[mi][1].x, bv.x, fmaf(av[mi][1].y, bv.y, acc[mi][ni][2]));
                            acc[mi][ni][3] = fmaf(av[mi][1].x, bv.z, fmaf(av[mi][1].y, bv.w, acc[mi][ni][3]));
                        }
                    }
                }
            }
        }
    }

    // ---------------- epilogue ----------------
    float cv0[4], cv1[4];
#pragma unroll
    for (int mi = 0; mi < 4; mi++) {
        int r0 = i0 + wm * 64 + mi * 16 + (lane >> 2);
        cv0[mi] = g_c[r0];
        cv1[mi] = g_c[r0 + 8];
    }
    float cjv[8][2];
#pragma unroll
    for (int ni = 0; ni < 8; ni++) {
        int cb = j0 + wn * 64 + (ni >> 1) * 16 + (ni & 1) * 8 + (lane & 3) * 2;
        cjv[ni][0] = g_cj[cb];
        cjv[ni][1] = g_cj[cb + 1];
    }

#pragma unroll
    for (int mi = 0; mi < 4; mi++) {
        const int r0 = i0 + wm * 64 + mi * 16 + (lane >> 2);
        const int r1 = r0 + 8;
        float rs0 = 0.f, rs1 = 0.f;
#pragma unroll
        for (int ni = 0; ni < 8; ni++) {
            const int cb = j0 + wn * 64 + (ni >> 1) * 16 + (ni & 1) * 8 + (lane & 3) * 2;
            float e0 = __expf(cv0[mi] + cjv[ni][0] - 0.1f * acc[mi][ni][0]);
            float e1 = __expf(cv0[mi] + cjv[ni][1] - 0.1f * acc[mi][ni][1]);
            float e2 = __expf(cv1[mi] + cjv[ni][0] - 0.1f * acc[mi][ni][2]);
            float e3 = __expf(cv1[mi] + cjv[ni][1] - 0.1f * acc[mi][ni][3]);
            if (cb     == r0) e0 = 0.f;
            if (cb + 1 == r0) e1 = 0.f;
            if (cb     == r1) e2 = 0.f;
            if (cb + 1 == r1) e3 = 0.f;
            rs0 += e0 + e1;
            rs1 += e2 + e3;
            if (write_logits) {
                if (cb     != r0) out[(size_t)r0 * NM1 + cb     - (cb     > r0)] = e0;
                if (cb + 1 != r0) out[(size_t)r0 * NM1 + cb + 1 - (cb + 1 > r0)] = e1;
                if (cb     != r1) out[(size_t)r1 * NM1 + cb     - (cb     > r1)] = e2;
                if (cb + 1 != r1) out[(size_t)r1 * NM1 + cb + 1 - (cb + 1 > r1)] = e3;
            }
        }
        rs0 += __shfl_xor_sync(0xFFFFFFFFu, rs0, 1);
        rs0 += __shfl_xor_sync(0xFFFFFFFFu, rs0, 2);
        rs1 += __shfl_xor_sync(0xFFFFFFFFu, rs1, 1);
        rs1 += __shfl_xor_sync(0xFFFFFFFFu, rs1, 2);
        if ((lane & 3) == 0) {
            atomicAdd(&g_rowsum[r0], rs0);
            atomicAdd(&g_rowsum[r1], rs1);
        }
    }
}

// ---------------- loss = mean(log(rowsum)) ----------------
__global__ void loss_kernel(float* __restrict__ loss_out) {
    __shared__ float sh[1024];
    float p = 0.f;
    for (int i = threadIdx.x; i < B2; i += 1024) p += __logf(g_rowsum[i]);
    sh[threadIdx.x] = p;
    __syncthreads();
    for (int st = 512; st > 0; st >>= 1) {
        if (threadIdx.x < st) sh[threadIdx.x] += sh[threadIdx.x + st];
        __syncthreads();
    }
    if (threadIdx.x == 0) *loss_out = sh[0] / (float)B2;
}

// ---------------- launch ----------------
extern "C" void kernel_launch(void* const* d_in, const int* in_sizes, int n_in,
                              void* d_out, int out_size) {
    const float* f     = (const float*)d_in[0];
    const float* s     = (const float*)d_in[1];
    const int*   label = (const int*)d_in[2];

    float* outf = (float*)d_out;
    const long long LOGN = (long long)B2 * NM1;
    float* loss_out  = nullptr;
    float* logit_out = nullptr;
    if ((long long)out_size == LOGN + 1) { loss_out = outf; logit_out = outf + 1; }
    else if ((long long)out_size == LOGN) { logit_out = outf; }
    else { loss_out = outf; }

    cudaFuncSetAttribute(dist_kernel, cudaFuncAttributeMaxDynamicSharedMemorySize, SM_TOTAL);

    prep_kernel<<<B2, 128>>>(f, s);
    gt_kernel<<<B2, 256>>>(f, s, label);

    dim3 grid(B2 / TN, B2 / TM);
    dist_kernel<<<grid, 256, SM_TOTAL>>>(logit_out ? logit_out : outf,
                                         logit_out != nullptr ? 1 : 0);

    if (loss_out) loss_kernel<<<1, 1024>>>(loss_out);
}

// round 10
// speedup vs baseline: 1.1635x; 1.1069x over previous
#include <cuda_runtime.h>
#include <cuda_bf16.h>
#include <cstdint>

#define B2   8192
#define D    512
#define KD   2048
#define NM1  8191

#define TM   256
#define TNM  96        // MMA columns per tile
#define TNF  32        // FMA columns per tile (total TN = 128)
#define BK   64
#define NSTG 3
#define NCH  48        // 3 products * 16 chunks

#define ROWB 144
#define A_SZ (256 * ROWB)              // 36864
#define B_SZ (96 * ROWB)               // 13824
#define STAGE_SZ (A_SZ + B_SZ)         // 50688
#define BBASE (NSTG * STAGE_SZ)        // 152064
#define BBLK  32768                    // one fp32 b-block (bx 16K + by 16K)
#define SM_TOTAL (BBASE + 2 * BBLK)    // 217600

// ---------------- device scratch ----------------
__device__ __align__(128) __nv_bfloat16 g_Abf[(size_t)B2 * KD];
__device__ __align__(128) __nv_bfloat16 g_Bbf[(size_t)B2 * KD];
__device__ __align__(128) float2 g_A32[(size_t)D * B2];   // (x^2, x)  d-major
__device__ __align__(128) float  g_B1[(size_t)D * B2];    // 1/s       d-major
__device__ __align__(128) float  g_B2[(size_t)D * B2];    // -2x/s     d-major
__device__ float g_t3[B2];
__device__ float g_ls[B2];
__device__ float g_c[B2];
__device__ float g_cj[B2];
__device__ float g_rowsum[B2];

// ---------------- PTX helpers ----------------
__device__ __forceinline__ uint32_t smem_u32(const void* p) {
    uint32_t a;
    asm("{ .reg .u64 t; cvta.to.shared.u64 t, %1; cvt.u32.u64 %0, t; }" : "=r"(a) : "l"(p));
    return a;
}
__device__ __forceinline__ void cp_async16(uint32_t dst, const void* src) {
    asm volatile("cp.async.cg.shared.global [%0], [%1], 16;" :: "r"(dst), "l"(src) : "memory");
}
__device__ __forceinline__ void cp_async8(uint32_t dst, const void* src) {
    asm volatile("cp.async.ca.shared.global [%0], [%1], 8;" :: "r"(dst), "l"(src) : "memory");
}
__device__ __forceinline__ void cp_commit() {
    asm volatile("cp.async.commit_group;" ::: "memory");
}
template <int N> __device__ __forceinline__ void cp_wait() {
    asm volatile("cp.async.wait_group %0;" :: "n"(N) : "memory");
}
__device__ __forceinline__ void ldsm4(uint32_t addr, uint32_t* r) {
    asm volatile("ldmatrix.sync.aligned.m8n8.x4.shared.b16 {%0,%1,%2,%3}, [%4];"
                 : "=r"(r[0]), "=r"(r[1]), "=r"(r[2]), "=r"(r[3]) : "r"(addr));
}
__device__ __forceinline__ void mma16816(float* d, const uint32_t* a,
                                         uint32_t b0, uint32_t b1) {
    asm volatile(
        "mma.sync.aligned.m16n8k16.row.col.f32.bf16.bf16.f32 "
        "{%0,%1,%2,%3}, {%4,%5,%6,%7}, {%8,%9}, {%0,%1,%2,%3};"
        : "+f"(d[0]), "+f"(d[1]), "+f"(d[2]), "+f"(d[3])
        : "r"(a[0]), "r"(a[1]), "r"(a[2]), "r"(a[3]), "r"(b0), "r"(b1));
}
__device__ __forceinline__ unsigned long long pack2(float lo, float hi) {
    unsigned long long r;
    asm("mov.b64 %0, {%1, %2};" : "=l"(r) : "f"(lo), "f"(hi));
    return r;
}
__device__ __forceinline__ void unpack2(unsigned long long v, float& lo, float& hi) {
    asm("mov.b64 {%0, %1}, %2;" : "=f"(lo), "=f"(hi) : "l"(v));
}
__device__ __forceinline__ void fma2(unsigned long long& d, unsigned long long a,
                                     unsigned long long b) {
    asm("fma.rn.f32x2 %0, %1, %2, %0;" : "+l"(d) : "l"(a), "l"(b));
}
__device__ __forceinline__ void barx(int id, int cnt) {
    asm volatile("bar.sync %0, %1;" :: "r"(id), "r"(cnt) : "memory");
}

// ---------------- prep ----------------
__global__ void prep_kernel(const float* __restrict__ f, const float* __restrict__ s) {
    int i = blockIdx.x;
    int t = threadIdx.x;  // 128
    const float* fr = f + (size_t)i * D;
    const float* sr = s + (size_t)i * D;
    __nv_bfloat16* Ar = g_Abf + (size_t)i * KD;
    __nv_bfloat16* Br = g_Bbf + (size_t)i * KD;
    float t3p = 0.f, lsp = 0.f;
    for (int d = t; d < D; d += 128) {
        float x = fr[d], sg = sr[d];
        float inv = 1.0f / sg;
        float a1 = x * x, a2 = x, b1 = inv, b2 = -2.0f * x * inv;
        __nv_bfloat16 h;
        h = __float2bfloat16(a1); Ar[d]       = h; Ar[1024 + d] = __float2bfloat16(a1 - __bfloat162float(h));
        h = __float2bfloat16(a2); Ar[512 + d] = h; Ar[1536 + d] = __float2bfloat16(a2 - __bfloat162float(h));
        h = __float2bfloat16(b1); Br[d]       = h; Br[1024 + d] = __float2bfloat16(b1 - __bfloat162float(h));
        h = __float2bfloat16(b2); Br[512 + d] = h; Br[1536 + d] = __float2bfloat16(b2 - __bfloat162float(h));
        g_A32[(size_t)d * B2 + i] = make_float2(a1, a2);
        g_B1[(size_t)d * B2 + i]  = b1;
        g_B2[(size_t)d * B2 + i]  = b2;
        t3p += a1 * inv;
        lsp += __logf(sg);
    }
    __shared__ float sh1[128], sh2[128];
    sh1[t] = t3p; sh2[t] = lsp;
    __syncthreads();
    for (int st = 64; st > 0; st >>= 1) {
        if (t < st) { sh1[t] += sh1[t + st]; sh2[t] += sh2[t + st]; }
        __syncthreads();
    }
    if (t == 0) { g_t3[i] = sh1[0]; g_ls[i] = sh2[0]; g_rowsum[i] = 0.f; }
}

// ---------------- gt + constants ----------------
__global__ void gt_kernel(const float* __restrict__ f, const float* __restrict__ s,
                          const int* __restrict__ label) {
    int i = blockIdx.x;
    int lab = label[i];
    int pos = lab + (lab >= i ? 1 : 0);
    const float* xi = f + (size_t)i * D;
    const float* xp = f + (size_t)pos * D;
    const float* sp = s + (size_t)pos * D;
    float p = 0.f;
    for (int d = threadIdx.x; d < D; d += 256) {
        float dd = xi[d] - xp[d];
        p += dd * dd / sp[d];
    }
    __shared__ float sh[256];
    sh[threadIdx.x] = p;
    __syncthreads();
    for (int st = 128; st > 0; st >>= 1) {
        if (threadIdx.x < st) sh[threadIdx.x] += sh[threadIdx.x + st];
        __syncthreads();
    }
    if (threadIdx.x == 0) {
        g_c[i]  = 0.1f * sh[0] + 0.5f * g_ls[i];
        g_cj[i] = -0.5f * g_ls[pos] - 0.1f * g_t3[i];
    }
}

// ---------------- MMA chunk loader (256 MMA threads) ----------------
__device__ __forceinline__ void load_chunk(int c, int st, int i0, int j0,
                                           uint32_t sb, int tid) {
    const int p  = c >> 4;
    const int kk = (c & 15) * BK;
    const int acol = (p == 2 ? 1024 : 0) + kk;
    const int bcol = (p == 1 ? 1024 : 0) + kk;
    const uint32_t aS = sb + st * STAGE_SZ;
    const uint32_t bS = aS + A_SZ;
#pragma unroll
    for (int it = 0; it < 8; it++) {            // A: 2048 16B segs
        int id = tid + it * 256;
        int row = id >> 3, kc = id & 7;
        cp_async16(aS + row * ROWB + kc * 16,
                   g_Abf + (size_t)(i0 + row) * KD + acol + kc * 8);
    }
#pragma unroll
    for (int it = 0; it < 3; it++) {            // B: 768 16B segs (96 rows)
        int id = tid + it * 256;
        int row = id >> 3, kc = id & 7;
        cp_async16(bS + row * ROWB + kc * 16,
                   g_Bbf + (size_t)(j0 + row) * KD + bcol + kc * 8);
    }
}

// ---------------- FMA b-block loader (128 FMA threads) ----------------
__device__ __forceinline__ void load_bblk(int blk, int buf, int j0,
                                          uint32_t sb, int ftid) {
    const uint32_t base = sb + BBASE + buf * BBLK;
#pragma unroll
    for (int it = 0; it < 16; it++) {           // bx: 2048 8B segs
        int id = ftid + it * 128;
        int dl = id >> 4, jp = id & 15;
        cp_async8(base + id * 8,
                  g_B1 + (size_t)(blk * 128 + dl) * B2 + j0 + TNM + jp * 2);
    }
#pragma unroll
    for (int it = 0; it < 16; it++) {           // by: 2048 8B segs
        int id = ftid + it * 128;
        int dl = id >> 4, jp = id & 15;
        cp_async8(base + 16384 + id * 8,
                  g_B2 + (size_t)(blk * 128 + dl) * B2 + j0 + TNM + jp * 2);
    }
}

// ---------------- main dual-pipe dist kernel ----------------
__global__ __launch_bounds__(384, 1)
void dist_kernel(float* __restrict__ out, int write_logits) {
    extern __shared__ char smem[];
    const uint32_t sb = smem_u32(smem);
    const int tid  = threadIdx.x;
    const int lane = tid & 31;
    const int wid  = tid >> 5;
    const int i0 = blockIdx.y * TM;
    const int j0 = blockIdx.x * 128;

    if (wid < 8) {
        // ================= MMA warps: cols [j0, j0+96) =================
        const int wm = wid & 3;
        const int wn = wid >> 2;

        float acc[4][6][4];
#pragma unroll
        for (int mi = 0; mi < 4; mi++)
#pragma unroll
            for (int ni = 0; ni < 6; ni++)
#pragma unroll
                for (int q = 0; q < 4; q++) acc[mi][ni][q] = 0.f;

#pragma unroll
        for (int s = 0; s < NSTG - 1; s++) { load_chunk(s, s, i0, j0, sb, tid); cp_commit(); }

        const uint32_t aoff = (wm * 64 + (lane & 15)) * ROWB + (lane >> 4) * 16;
        const uint32_t boff = (wn * 48 + (lane & 15)) * ROWB + (lane >> 4) * 16;

        uint32_t afr[2][4][4], bfr[2][3][4];

        for (int c = 0; c < NCH; c++) {
            cp_wait<1>();
            barx(1, 256);
            int pf = c + NSTG - 1;
            if (pf < NCH) { load_chunk(pf, pf % NSTG, i0, j0, sb, tid); cp_commit(); }

            const uint32_t aS = sb + (c % NSTG) * STAGE_SZ;
            const uint32_t bS = aS + A_SZ;

#pragma unroll
            for (int mi = 0; mi < 4; mi++) ldsm4(aS + aoff + mi * (16 * ROWB), afr[0][mi]);
#pragma unroll
            for (int np = 0; np < 3; np++) ldsm4(bS + boff + np * (16 * ROWB), bfr[0][np]);

#pragma unroll
            for (int ks = 0; ks < 4; ks++) {
                const int cur = ks & 1, nxt = cur ^ 1;
                if (ks < 3) {
#pragma unroll
                    for (int mi = 0; mi < 4; mi++)
                        ldsm4(aS + aoff + mi * (16 * ROWB) + (ks + 1) * 32, afr[nxt][mi]);
#pragma unroll
                    for (int np = 0; np < 3; np++)
                        ldsm4(bS + boff + np * (16 * ROWB) + (ks + 1) * 32, bfr[nxt][np]);
                }
#pragma unroll
                for (int mi = 0; mi < 4; mi++)
#pragma unroll
                    for (int ni = 0; ni < 6; ni++)
                        mma16816(acc[mi][ni], afr[cur][mi],
                                 bfr[cur][ni >> 1][ni & 1], bfr[cur][ni >> 1][(ni & 1) + 2]);
            }
        }

        // ---- MMA epilogue ----
        float cv0[4], cv1[4];
#pragma unroll
        for (int mi = 0; mi < 4; mi++) {
            int r0 = i0 + wm * 64 + mi * 16 + (lane >> 2);
            cv0[mi] = g_c[r0];
            cv1[mi] = g_c[r0 + 8];
        }
        float cjv[6][2];
#pragma unroll
        for (int ni = 0; ni < 6; ni++) {
            int cb = j0 + wn * 48 + (ni >> 1) * 16 + (ni & 1) * 8 + (lane & 3) * 2;
            cjv[ni][0] = g_cj[cb];
            cjv[ni][1] = g_cj[cb + 1];
        }
#pragma unroll
        for (int mi = 0; mi < 4; mi++) {
            const int r0 = i0 + wm * 64 + mi * 16 + (lane >> 2);
            const int r1 = r0 + 8;
            float rs0 = 0.f, rs1 = 0.f;
#pragma unroll
            for (int ni = 0; ni < 6; ni++) {
                const int cb = j0 + wn * 48 + (ni >> 1) * 16 + (ni & 1) * 8 + (lane & 3) * 2;
                float e0 = __expf(cv0[mi] + cjv[ni][0] - 0.1f * acc[mi][ni][0]);
                float e1 = __expf(cv0[mi] + cjv[ni][1] - 0.1f * acc[mi][ni][1]);
                float e2 = __expf(cv1[mi] + cjv[ni][0] - 0.1f * acc[mi][ni][2]);
                float e3 = __expf(cv1[mi] + cjv[ni][1] - 0.1f * acc[mi][ni][3]);
                if (cb     == r0) e0 = 0.f;
                if (cb + 1 == r0) e1 = 0.f;
                if (cb     == r1) e2 = 0.f;
                if (cb + 1 == r1) e3 = 0.f;
                rs0 += e0 + e1;
                rs1 += e2 + e3;
                if (write_logits) {
                    if (cb     != r0) out[(size_t)r0 * NM1 + cb     - (cb     > r0)] = e0;
                    if (cb + 1 != r0) out[(size_t)r0 * NM1 + cb + 1 - (cb + 1 > r0)] = e1;
                    if (cb     != r1) out[(size_t)r1 * NM1 + cb     - (cb     > r1)] = e2;
                    if (cb + 1 != r1) out[(size_t)r1 * NM1 + cb + 1 - (cb + 1 > r1)] = e3;
                }
            }
            rs0 += __shfl_xor_sync(0xFFFFFFFFu, rs0, 1);
            rs0 += __shfl_xor_sync(0xFFFFFFFFu, rs0, 2);
            rs1 += __shfl_xor_sync(0xFFFFFFFFu, rs1, 1);
            rs1 += __shfl_xor_sync(0xFFFFFFFFu, rs1, 2);
            if ((lane & 3) == 0) {
                atomicAdd(&g_rowsum[r0], rs0);
                atomicAdd(&g_rowsum[r1], rs1);
            }
        }
    } else {
        // ================= FMA warps: cols [j0+96, j0+128), exact fp32 =================
        const int ftid = tid - 256;          // 0..127
        const int fw   = wid - 8;            // 0..3
        const int rA   = fw * 64 + lane;     // local rows within 256
        const int rB   = rA + 32;

        unsigned long long acc2[2][16];
#pragma unroll
        for (int r = 0; r < 2; r++)
#pragma unroll
            for (int jp = 0; jp < 16; jp++) acc2[r][jp] = 0ull;

        load_bblk(0, 0, j0, sb, ftid);
        cp_commit();

        for (int blk = 0; blk < 4; blk++) {
            if (blk + 1 < 4) load_bblk(blk + 1, (blk + 1) & 1, j0, sb, ftid);
            cp_commit();
            cp_wait<1>();
            barx(2, 128);

            const char* bx = smem + BBASE + (blk & 1) * BBLK;
            const char* by = bx + 16384;
            const char* ap = (const char*)(g_A32 + (size_t)blk * 128 * B2 + i0);

#pragma unroll 2
            for (int dl = 0; dl < 128; dl++) {
                float2 a0 = *(const float2*)(ap + (size_t)dl * (B2 * 8) + rA * 8);
                float2 a1 = *(const float2*)(ap + (size_t)dl * (B2 * 8) + rB * 8);
                unsigned long long axx = pack2(a0.x, a0.x);
                unsigned long long ayy = pack2(a0.y, a0.y);
                unsigned long long bxx = pack2(a1.x, a1.x);
                unsigned long long byy = pack2(a1.y, a1.y);
#pragma unroll
                for (int jp = 0; jp < 16; jp++) {
                    unsigned long long vx = *(const unsigned long long*)(bx + (dl * 16 + jp) * 8);
                    unsigned long long vy = *(const unsigned long long*)(by + (dl * 16 + jp) * 8);
                    fma2(acc2[0][jp], axx, vx);
                    fma2(acc2[0][jp], ayy, vy);
                    fma2(acc2[1][jp], bxx, vx);
                    fma2(acc2[1][jp], byy, vy);
                }
            }
            barx(2, 128);   // all warps done with this buffer before overwrite
        }

        // ---- FMA epilogue: exp, rowsum, smem transpose, coalesced store ----
        const int igA = i0 + rA;
        const int igB = i0 + rB;
        const float cvA = g_c[igA];
        const float cvB = g_c[igB];
        float* buf = (float*)(smem + BBASE + fw * 8448);

        float rsA = 0.f, rsB = 0.f;
#pragma unroll
        for (int jp = 0; jp < 16; jp++) {
            float dA0, dA1, dB0, dB1;
            unpack2(acc2[0][jp], dA0, dA1);
            unpack2(acc2[1][jp], dB0, dB1);
            int c0 = jp * 2, c1 = jp * 2 + 1;
            int jg0 = j0 + TNM + c0, jg1 = j0 + TNM + c1;
            float cj0 = g_cj[jg0], cj1 = g_cj[jg1];
            float eA0 = __expf(cvA + cj0 - 0.1f * dA0);
            float eA1 = __expf(cvA + cj1 - 0.1f * dA1);
            float eB0 = __expf(cvB + cj0 - 0.1f * dB0);
            float eB1 = __expf(cvB + cj1 - 0.1f * dB1);
            if (jg0 == igA) eA0 = 0.f;
            if (jg1 == igA) eA1 = 0.f;
            if (jg0 == igB) eB0 = 0.f;
            if (jg1 == igB) eB1 = 0.f;
            rsA += eA0 + eA1;
            rsB += eB0 + eB1;
            buf[lane * 33 + c0]        = eA0;
            buf[lane * 33 + c1]        = eA1;
            buf[(lane + 32) * 33 + c0] = eB0;
            buf[(lane + 32) * 33 + c1] = eB1;
        }
        atomicAdd(&g_rowsum[igA], rsA);
        atomicAdd(&g_rowsum[igB], rsB);
        __syncwarp();
        if (write_logits) {
            const int jg = j0 + TNM + lane;
#pragma unroll 4
            for (int r = 0; r < 64; r++) {
                const int ig = i0 + fw * 64 + r;
                float v = buf[r * 33 + lane];
                if (jg != ig)
                    out[(size_t)ig * NM1 + jg - (jg > ig ? 1 : 0)] = v;
            }
        }
    }
}

// ---------------- loss = mean(log(rowsum)) ----------------
__global__ void loss_kernel(float* __restrict__ loss_out) {
    __shared__ float sh[1024];
    float p = 0.f;
    for (int i = threadIdx.x; i < B2; i += 1024) p += __logf(g_rowsum[i]);
    sh[threadIdx.x] = p;
    __syncthreads();
    for (int st = 512; st > 0; st >>= 1) {
        if (threadIdx.x < st) sh[threadIdx.x] += sh[threadIdx.x + st];
        __syncthreads();
    }
    if (threadIdx.x == 0) *loss_out = sh[0] / (float)B2;
}

// ---------------- launch ----------------
extern "C" void kernel_launch(void* const* d_in, const int* in_sizes, int n_in,
                              void* d_out, int out_size) {
    const float* f     = (const float*)d_in[0];
    const float* s     = (const float*)d_in[1];
    const int*   label = (const int*)d_in[2];

    float* outf = (float*)d_out;
    const long long LOGN = (long long)B2 * NM1;
    float* loss_out  = nullptr;
    float* logit_out = nullptr;
    if ((long long)out_size == LOGN + 1) { loss_out = outf; logit_out = outf + 1; }
    else if ((long long)out_size == LOGN) { logit_out = outf; }
    else { loss_out = outf; }

    cudaFuncSetAttribute(dist_kernel, cudaFuncAttributeMaxDynamicSharedMemorySize, SM_TOTAL);

    prep_kernel<<<B2, 128>>>(f, s);
    gt_kernel<<<B2, 256>>>(f, s, label);

    dim3 grid(B2 / 128, B2 / TM);
    dist_kernel<<<grid, 384, SM_TOTAL>>>(logit_out ? logit_out : outf,
                                         logit_out != nullptr ? 1 : 0);

    if (loss_out) loss_kernel<<<1, 1024>>>(loss_out);
}

// round 11
// speedup vs baseline: 1.8914x; 1.6257x over previous
#include <cuda_runtime.h>
#include <cuda_fp16.h>
#include <cstdint>

#define B2   8192
#define D    512
#define KD   2048      // fp16 cols: [0,1024) hi, [1024,2048) lo
#define NM1  8191

#define TM   256
#define TN   128
#define BK   64        // fp16 per chunk (128 B rows)
#define NSTG 3
#define NCH  48        // 32 cross (K=2048, fp16 acc) + 16 hihi (K=1024, fp32 acc)

#define ROWB 144                       // 128 B data + 16 B pad
#define A_SZ (256 * ROWB)              // 36864
#define B_SZ (128 * ROWB)              // 18432
#define STAGE_SZ (A_SZ + B_SZ)         // 55296
#define SM_TOTAL (NSTG * STAGE_SZ)     // 165888

// ---------------- device scratch ----------------
__device__ __align__(128) __half g_Ah[(size_t)B2 * KD];  // [hi(x^2)|hi(x)|lo(x^2)|lo(x)]
__device__ __align__(128) __half g_Bh[(size_t)B2 * KD];  // [hi(1/s)|hi(-2x/s)|lo(1/s)|lo(-2x/s)]
__device__ float g_t3[B2];
__device__ float g_ls[B2];
__device__ float g_c[B2];      // 0.1*gt_i + 0.5*ls_i
__device__ float g_cj[B2];     // -0.5*ls[pos(j)] - 0.1*t3[j]
__device__ float g_rowsum[B2];

// ---------------- PTX helpers ----------------
__device__ __forceinline__ uint32_t smem_u32(const void* p) {
    uint32_t a;
    asm("{ .reg .u64 t; cvta.to.shared.u64 t, %1; cvt.u32.u64 %0, t; }" : "=r"(a) : "l"(p));
    return a;
}
__device__ __forceinline__ void cp_async16(uint32_t dst, const void* src) {
    asm volatile("cp.async.cg.shared.global [%0], [%1], 16;" :: "r"(dst), "l"(src) : "memory");
}
__device__ __forceinline__ void cp_commit() {
    asm volatile("cp.async.commit_group;" ::: "memory");
}
template <int N> __device__ __forceinline__ void cp_wait() {
    asm volatile("cp.async.wait_group %0;" :: "n"(N) : "memory");
}
__device__ __forceinline__ void ldsm4(uint32_t addr, uint32_t* r) {
    asm volatile("ldmatrix.sync.aligned.m8n8.x4.shared.b16 {%0,%1,%2,%3}, [%4];"
                 : "=r"(r[0]), "=r"(r[1]), "=r"(r[2]), "=r"(r[3]) : "r"(addr));
}
// fp16 x fp16 -> fp32 accum
__device__ __forceinline__ void mma_f32(float* d, const uint32_t* a,
                                        uint32_t b0, uint32_t b1) {
    asm volatile(
        "mma.sync.aligned.m16n8k16.row.col.f32.f16.f16.f32 "
        "{%0,%1,%2,%3}, {%4,%5,%6,%7}, {%8,%9}, {%0,%1,%2,%3};"
        : "+f"(d[0]), "+f"(d[1]), "+f"(d[2]), "+f"(d[3])
        : "r"(a[0]), "r"(a[1]), "r"(a[2]), "r"(a[3]), "r"(b0), "r"(b1));
}
// fp16 x fp16 -> fp16 accum (rate-test path)
__device__ __forceinline__ void mma_f16(uint32_t* d, const uint32_t* a,
                                        uint32_t b0, uint32_t b1) {
    asm volatile(
        "mma.sync.aligned.m16n8k16.row.col.f16.f16.f16.f16 "
        "{%0,%1}, {%2,%3,%4,%5}, {%6,%7}, {%0,%1};"
        : "+r"(d[0]), "+r"(d[1])
        : "r"(a[0]), "r"(a[1]), "r"(a[2]), "r"(a[3]), "r"(b0), "r"(b1));
}

// ---------------- prep: fp16 hi/lo splits + t3 + ls ----------------
__global__ void prep_kernel(const float* __restrict__ f, const float* __restrict__ s) {
    int i = blockIdx.x;
    int t = threadIdx.x;  // 128
    const float* fr = f + (size_t)i * D;
    const float* sr = s + (size_t)i * D;
    __half* Ar = g_Ah + (size_t)i * KD;
    __half* Br = g_Bh + (size_t)i * KD;
    float t3p = 0.f, lsp = 0.f;
    for (int d = t; d < D; d += 128) {
        float x = fr[d], sg = sr[d];
        float inv = 1.0f / sg;
        float a1 = x * x, a2 = x, b1 = inv, b2 = -2.0f * x * inv;
        __half h;
        h = __float2half_rn(a1); Ar[d]       = h; Ar[1024 + d] = __float2half_rn(a1 - __half2float(h));
        h = __float2half_rn(a2); Ar[512 + d] = h; Ar[1536 + d] = __float2half_rn(a2 - __half2float(h));
        h = __float2half_rn(b1); Br[d]       = h; Br[1024 + d] = __float2half_rn(b1 - __half2float(h));
        h = __float2half_rn(b2); Br[512 + d] = h; Br[1536 + d] = __float2half_rn(b2 - __half2float(h));
        t3p += a1 * inv;
        lsp += logf(sg);
    }
    __shared__ float sh1[128], sh2[128];
    sh1[t] = t3p; sh2[t] = lsp;
    __syncthreads();
    for (int st = 64; st > 0; st >>= 1) {
        if (t < st) { sh1[t] += sh1[t + st]; sh2[t] += sh2[t + st]; }
        __syncthreads();
    }
    if (t == 0) { g_t3[i] = sh1[0]; g_ls[i] = sh2[0]; g_rowsum[i] = 0.f; }
}

// ---------------- gt + per-row/col constants ----------------
__global__ void gt_kernel(const float* __restrict__ f, const float* __restrict__ s,
                          const int* __restrict__ label) {
    int i = blockIdx.x;
    int lab = label[i];
    int pos = lab + (lab >= i ? 1 : 0);
    const float* xi = f + (size_t)i * D;
    const float* xp = f + (size_t)pos * D;
    const float* sp = s + (size_t)pos * D;
    float p = 0.f;
    for (int d = threadIdx.x; d < D; d += 256) {
        float dd = xi[d] - xp[d];
        p += dd * dd / sp[d];
    }
    __shared__ float sh[256];
    sh[threadIdx.x] = p;
    __syncthreads();
    for (int st = 128; st > 0; st >>= 1) {
        if (threadIdx.x < st) sh[threadIdx.x] += sh[threadIdx.x + st];
        __syncthreads();
    }
    if (threadIdx.x == 0) {
        g_c[i]  = 0.1f * sh[0] + 0.5f * g_ls[i];
        g_cj[i] = -0.5f * g_ls[pos] - 0.1f * g_t3[i];
    }
}

// ---------------- chunk loader (BK=64) ----------------
// chunks 0..31:  cross — A col c*64 over [hi|lo], B col +1024 mod 2048 ([lo|hi])
// chunks 32..47: hihi  — A,B cols (c-32)*64 in [0,1024)
__device__ __forceinline__ void load_chunk(int c, int st, int i0, int j0, uint32_t sb) {
    int acol, bcol;
    if (c < 32) { acol = c * 64; bcol = (acol + 1024) & 2047; }
    else        { acol = (c - 32) * 64; bcol = acol; }
    const uint32_t aS = sb + st * STAGE_SZ;
    const uint32_t bS = aS + A_SZ;
    const int tid = threadIdx.x;
#pragma unroll
    for (int it = 0; it < 8; it++) {            // A: 2048 16B segs
        int id = tid + it * 256;
        int row = id >> 3, kc = id & 7;
        cp_async16(aS + row * ROWB + kc * 16,
                   g_Ah + (size_t)(i0 + row) * KD + acol + kc * 8);
    }
#pragma unroll
    for (int it = 0; it < 4; it++) {            // B: 1024 16B segs
        int id = tid + it * 256;
        int row = id >> 3, kc = id & 7;
        cp_async16(bS + row * ROWB + kc * 16,
                   g_Bh + (size_t)(j0 + row) * KD + bcol + kc * 8);
    }
}

// ---------------- main dist kernel: fp16-acc cross + fp32-acc hihi ----------
__global__ __launch_bounds__(256)
void dist_kernel(float* __restrict__ out, int write_logits) {
    extern __shared__ char smem[];
    const uint32_t sb = smem_u32(smem);
    const int tid  = threadIdx.x;
    const int lane = tid & 31;
    const int wid  = tid >> 5;
    const int wm   = wid & 3;
    const int wn   = wid >> 2;
    const int i0 = blockIdx.y * TM;
    const int j0 = blockIdx.x * TN;

    // prologue: stages 0,1
#pragma unroll
    for (int s = 0; s < NSTG - 1; s++) { load_chunk(s, s, i0, j0, sb); cp_commit(); }

    const uint32_t aoff = (wm * 64 + (lane & 15)) * ROWB + (lane >> 4) * 16;
    const uint32_t boff = (wn * 64 + (lane & 15)) * ROWB + (lane >> 4) * 16;

    uint32_t afr[2][4][4], bfr[2][4][4];

    // ---------------- phase A: cross (chunks 0..31, fp16 accum) ----------------
    uint32_t acch[4][8][2];
#pragma unroll
    for (int mi = 0; mi < 4; mi++)
#pragma unroll
        for (int ni = 0; ni < 8; ni++) { acch[mi][ni][0] = 0u; acch[mi][ni][1] = 0u; }

    for (int c = 0; c < 32; c++) {
        cp_wait<1>();
        __syncthreads();
        int pf = c + NSTG - 1;
        load_chunk(pf, pf % NSTG, i0, j0, sb);
        cp_commit();

        const uint32_t aS = sb + (c % NSTG) * STAGE_SZ;
        const uint32_t bS = aS + A_SZ;
#pragma unroll
        for (int mi = 0; mi < 4; mi++) ldsm4(aS + aoff + mi * (16 * ROWB), afr[0][mi]);
#pragma unroll
        for (int np = 0; np < 4; np++) ldsm4(bS + boff + np * (16 * ROWB), bfr[0][np]);
#pragma unroll
        for (int ks = 0; ks < 4; ks++) {
            const int cur = ks & 1, nxt = cur ^ 1;
            if (ks < 3) {
#pragma unroll
                for (int mi = 0; mi < 4; mi++)
                    ldsm4(aS + aoff + mi * (16 * ROWB) + (ks + 1) * 32, afr[nxt][mi]);
#pragma unroll
                for (int np = 0; np < 4; np++)
                    ldsm4(bS + boff + np * (16 * ROWB) + (ks + 1) * 32, bfr[nxt][np]);
            }
#pragma unroll
            for (int mi = 0; mi < 4; mi++)
#pragma unroll
                for (int ni = 0; ni < 8; ni++)
                    mma_f16(acch[mi][ni], afr[cur][mi],
                            bfr[cur][ni >> 1][ni & 1], bfr[cur][ni >> 1][(ni & 1) + 2]);
        }
    }

    // convert cross fp16 accumulators to fp32
    float acc[4][8][4];
#pragma unroll
    for (int mi = 0; mi < 4; mi++)
#pragma unroll
        for (int ni = 0; ni < 8; ni++) {
            __half2 h0 = *(__half2*)&acch[mi][ni][0];
            __half2 h1 = *(__half2*)&acch[mi][ni][1];
            acc[mi][ni][0] = __low2float(h0);
            acc[mi][ni][1] = __high2float(h0);
            acc[mi][ni][2] = __low2float(h1);
            acc[mi][ni][3] = __high2float(h1);
        }

    // ---------------- phase B: hihi (chunks 32..47, fp32 accum) ----------------
    for (int c = 32; c < NCH; c++) {
        cp_wait<1>();
        __syncthreads();
        int pf = c + NSTG - 1;
        if (pf < NCH) { load_chunk(pf, pf % NSTG, i0, j0, sb); cp_commit(); }

        const uint32_t aS = sb + (c % NSTG) * STAGE_SZ;
        const uint32_t bS = aS + A_SZ;
#pragma unroll
        for (int mi = 0; mi < 4; mi++) ldsm4(aS + aoff + mi * (16 * ROWB), afr[0][mi]);
#pragma unroll
        for (int np = 0; np < 4; np++) ldsm4(bS + boff + np * (16 * ROWB), bfr[0][np]);
#pragma unroll
        for (int ks = 0; ks < 4; ks++) {
            const int cur = ks & 1, nxt = cur ^ 1;
            if (ks < 3) {
#pragma unroll
                for (int mi = 0; mi < 4; mi++)
                    ldsm4(aS + aoff + mi * (16 * ROWB) + (ks + 1) * 32, afr[nxt][mi]);
#pragma unroll
                for (int np = 0; np < 4; np++)
                    ldsm4(bS + boff + np * (16 * ROWB) + (ks + 1) * 32, bfr[nxt][np]);
            }
#pragma unroll
            for (int mi = 0; mi < 4; mi++)
#pragma unroll
                for (int ni = 0; ni < 8; ni++)
                    mma_f32(acc[mi][ni], afr[cur][mi],
                            bfr[cur][ni >> 1][ni & 1], bfr[cur][ni >> 1][(ni & 1) + 2]);
        }
    }

    // ---------------- epilogue ----------------
    float cv0[4], cv1[4];
#pragma unroll
    for (int mi = 0; mi < 4; mi++) {
        int r0 = i0 + wm * 64 + mi * 16 + (lane >> 2);
        cv0[mi] = g_c[r0];
        cv1[mi] = g_c[r0 + 8];
    }
    float cjv[8][2];
#pragma unroll
    for (int ni = 0; ni < 8; ni++) {
        int cb = j0 + wn * 64 + (ni >> 1) * 16 + (ni & 1) * 8 + (lane & 3) * 2;
        cjv[ni][0] = g_cj[cb];
        cjv[ni][1] = g_cj[cb + 1];
    }

#pragma unroll
    for (int mi = 0; mi < 4; mi++) {
        const int r0 = i0 + wm * 64 + mi * 16 + (lane >> 2);
        const int r1 = r0 + 8;
        float rs0 = 0.f, rs1 = 0.f;
#pragma unroll
        for (int ni = 0; ni < 8; ni++) {
            const int cb = j0 + wn * 64 + (ni >> 1) * 16 + (ni & 1) * 8 + (lane & 3) * 2;
            float e0 = __expf(cv0[mi] + cjv[ni][0] - 0.1f * acc[mi][ni][0]);
            float e1 = __expf(cv0[mi] + cjv[ni][1] - 0.1f * acc[mi][ni][1]);
            float e2 = __expf(cv1[mi] + cjv[ni][0] - 0.1f * acc[mi][ni][2]);
            float e3 = __expf(cv1[mi] + cjv[ni][1] - 0.1f * acc[mi][ni][3]);
            if (cb     == r0) e0 = 0.f;
            if (cb + 1 == r0) e1 = 0.f;
            if (cb     == r1) e2 = 0.f;
            if (cb + 1 == r1) e3 = 0.f;
            rs0 += e0 + e1;
            rs1 += e2 + e3;
            if (write_logits) {
                if (cb     != r0) out[(size_t)r0 * NM1 + cb     - (cb     > r0)] = e0;
                if (cb + 1 != r0) out[(size_t)r0 * NM1 + cb + 1 - (cb + 1 > r0)] = e1;
                if (cb     != r1) out[(size_t)r1 * NM1 + cb     - (cb     > r1)] = e2;
                if (cb + 1 != r1) out[(size_t)r1 * NM1 + cb + 1 - (cb + 1 > r1)] = e3;
            }
        }
        rs0 += __shfl_xor_sync(0xFFFFFFFFu, rs0, 1);
        rs0 += __shfl_xor_sync(0xFFFFFFFFu, rs0, 2);
        rs1 += __shfl_xor_sync(0xFFFFFFFFu, rs1, 1);
        rs1 += __shfl_xor_sync(0xFFFFFFFFu, rs1, 2);
        if ((lane & 3) == 0) {
            atomicAdd(&g_rowsum[r0], rs0);
            atomicAdd(&g_rowsum[r1], rs1);
        }
    }
}

// ---------------- loss = mean(log(rowsum)) ----------------
__global__ void loss_kernel(float* __restrict__ loss_out) {
    __shared__ float sh[1024];
    float p = 0.f;
    for (int i = threadIdx.x; i < B2; i += 1024) p += logf(g_rowsum[i]);
    sh[threadIdx.x] = p;
    __syncthreads();
    for (int st = 512; st > 0; st >>= 1) {
        if (threadIdx.x < st) sh[threadIdx.x] += sh[threadIdx.x + st];
        __syncthreads();
    }
    if (threadIdx.x == 0) *loss_out = sh[0] / (float)B2;
}

// ---------------- launch ----------------
extern "C" void kernel_launch(void* const* d_in, const int* in_sizes, int n_in,
                              void* d_out, int out_size) {
    const float* f     = (const float*)d_in[0];
    const float* s     = (const float*)d_in[1];
    const int*   label = (const int*)d_in[2];

    float* outf = (float*)d_out;
    const long long LOGN = (long long)B2 * NM1;
    float* loss_out  = nullptr;
    float* logit_out = nullptr;
    if ((long long)out_size == LOGN + 1) { loss_out = outf; logit_out = outf + 1; }
    else if ((long long)out_size == LOGN) { logit_out = outf; }
    else { loss_out = outf; }

    cudaFuncSetAttribute(dist_kernel, cudaFuncAttributeMaxDynamicSharedMemorySize, SM_TOTAL);

    prep_kernel<<<B2, 128>>>(f, s);
    gt_kernel<<<B2, 256>>>(f, s, label);

    dim3 grid(B2 / TN, B2 / TM);
    dist_kernel<<<grid, 256, SM_TOTAL>>>(logit_out ? logit_out : outf,
                                         logit_out != nullptr ? 1 : 0);

    if (loss_out) loss_kernel<<<1, 1024>>>(loss_out);
}